// round 3
// baseline (speedup 1.0000x reference)
#include <cuda_runtime.h>
#include <cstdint>

#define B 8
#define T 4096
#define D 1024
#define S 64
#define SLOT_DIM 256
#define BOND 32
#define NQ 8
#define QDIM 256
#define TCHUNK 64
#define NCHUNK (T / TCHUNK)  // 64

// ------- device scratch (no allocations allowed) -------
__device__ float g_part[B * NCHUNK * D];   // 2 MB
__device__ int   g_cnt[B];                 // zero-initialized; reset after use
__device__ float g_m0[B * NQ];
__device__ float g_m1[B * NQ];
__device__ float g_overlaps[B * S];
__device__ float g_feats[S * NQ];
__device__ float g_bias[B * D];

// ========== Kernel 1: partial column sums + (last block per batch) query ==========
// grid (NCHUNK, B), 256 threads.
__global__ void k_partsum_query(const float* __restrict__ x,
                                const float* __restrict__ Wq,
                                const float* __restrict__ bq) {
    const int c = blockIdx.x;
    const int b = blockIdx.y;
    const int tid = threadIdx.x;

    // ---- partial sum over TCHUNK rows ----
    {
        const float4* xp = reinterpret_cast<const float4*>(x) +
                           ((size_t)b * T + (size_t)c * TCHUNK) * (D / 4);
        float4 acc = make_float4(0.f, 0.f, 0.f, 0.f);
#pragma unroll 8
        for (int t = 0; t < TCHUNK; ++t) {
            float4 v = xp[t * (D / 4) + tid];
            acc.x += v.x; acc.y += v.y; acc.z += v.z; acc.w += v.w;
        }
        reinterpret_cast<float4*>(g_part)[(b * NCHUNK + c) * (D / 4) + tid] = acc;
    }

    // ---- last-block-done detection ----
    __threadfence();
    __shared__ bool is_last;
    if (tid == 0) {
        int old = atomicAdd(&g_cnt[b], 1);
        is_last = (old == NCHUNK - 1);
    }
    __syncthreads();
    if (!is_last) return;

    // ---- final reduction: xs[d] = mean over t ----
    __shared__ float xs[D];
    __shared__ float qa[QDIM];
    __shared__ float red[8];
    {
        const float* p = g_part + (size_t)b * NCHUNK * D;
#pragma unroll
        for (int i = 0; i < 4; ++i) {
            const int d = tid + i * 256;
            float acc = 0.f;
#pragma unroll 16
            for (int cc = 0; cc < NCHUNK; ++cc) acc += p[cc * D + d];
            xs[d] = acc * (1.0f / (float)T);
        }
    }
    __syncthreads();

    // ---- GEMV logits (thread j = column j), 4-way ILP ----
    const int j = tid;
    float a0 = 0.f, a1 = 0.f, a2 = 0.f, a3 = 0.f;
#pragma unroll 4
    for (int k = 0; k < D; k += 4) {
        a0 = fmaf(xs[k + 0], Wq[(size_t)(k + 0) * QDIM + j], a0);
        a1 = fmaf(xs[k + 1], Wq[(size_t)(k + 1) * QDIM + j], a1);
        a2 = fmaf(xs[k + 2], Wq[(size_t)(k + 2) * QDIM + j], a2);
        a3 = fmaf(xs[k + 3], Wq[(size_t)(k + 3) * QDIM + j], a3);
    }
    float logit = (a0 + a1) + (a2 + a3) + bq[j];

    // ---- softmax over 256 ----
    float m = logit;
#pragma unroll
    for (int o = 16; o; o >>= 1) m = fmaxf(m, __shfl_xor_sync(0xffffffffu, m, o));
    if ((tid & 31) == 0) red[tid >> 5] = m;
    __syncthreads();
    float bm = red[0];
#pragma unroll
    for (int i = 1; i < 8; ++i) bm = fmaxf(bm, red[i]);
    float e = __expf(logit - bm);
    float ssum = e;
#pragma unroll
    for (int o = 16; o; o >>= 1) ssum += __shfl_xor_sync(0xffffffffu, ssum, o);
    __syncthreads();
    if ((tid & 31) == 0) red[tid >> 5] = ssum;
    __syncthreads();
    float tot = 0.f;
#pragma unroll
    for (int i = 0; i < 8; ++i) tot += red[i];
    qa[j] = e / tot;
    __syncthreads();

    // ---- amplitude means (JAX OOB-clamp to index 255) ----
    if (tid < 16) {
        const int q = tid & 7;
        const bool one = tid >= 8;
        const int s = 1 << (7 - q);
        const int cin = min(s, 128 / s);
        float a = 0.f;
        const int off = one ? s : 0;
        for (int i = 0; i < cin; ++i) a += qa[i * 2 * s + off];
        a += (float)(s - cin) * qa[QDIM - 1];
        float* dst = one ? g_m1 : g_m0;
        dst[b * NQ + q] = a / (float)s;
    }

    // reset counter for the next graph replay
    if (tid == 0) g_cnt[b] = 0;
}

// ====== Kernel 2: per-slot feats + MPS contraction overlaps ======
// grid (S), 256 threads = 8 warps; cm slice staged in shared (48 KB).
__global__ void k_slots(const float* __restrict__ cf,
                        const float* __restrict__ cm,
                        const float* __restrict__ cl) {
    const int s = blockIdx.x;
    const int tid = threadIdx.x;
    const int w = tid >> 5;
    const int lane = tid & 31;
    __shared__ float s_cm[12288];   // 48 KB: 6 levels x 32 x 64

    {
        const float4* src = reinterpret_cast<const float4*>(cm + (size_t)s * 12288);
        float4* dst = reinterpret_cast<float4*>(s_cm);
#pragma unroll
        for (int i = 0; i < 12; ++i)
            dst[i * 256 + tid] = src[i * 256 + tid];
    }
    __syncthreads();

    // ---- feats ----
    float fsum;
    float inv_cnt;
    if (w == 0) {
        fsum = cf[s * 64 + lane] + cf[s * 64 + 32 + lane];
        inv_cnt = 1.0f / 64.0f;
    } else if (w == 7) {
        fsum = cl[s * 64 + lane] + cl[s * 64 + 32 + lane];
        inv_cnt = 1.0f / 64.0f;
    } else {
        const float* base = s_cm + (w - 1) * 2048;
        fsum = 0.f;
#pragma unroll
        for (int i = 0; i < 64; ++i) fsum += base[i * 32 + lane];
        inv_cnt = 1.0f / 2048.0f;
    }
#pragma unroll
    for (int o = 16; o; o >>= 1) fsum += __shfl_xor_sync(0xffffffffu, fsum, o);
    if (lane == 0) g_feats[s * NQ + w] = fsum * inv_cnt;

    // ---- overlap for batch b = w ----
    const int b = w;
    float M0[NQ], M1[NQ];
#pragma unroll
    for (int q = 0; q < NQ; ++q) {
        M0[q] = g_m0[b * NQ + q];
        M1[q] = g_m1[b * NQ + q];
    }
    float v = M0[0] * cf[s * 64 + lane] + M1[0] * cf[s * 64 + 32 + lane];
#pragma unroll
    for (int q = 1; q <= NQ - 2; ++q) {
        const float* base = s_cm + (q - 1) * 2048;
        float nv = 0.f;
#pragma unroll 8
        for (int l = 0; l < BOND; ++l) {
            float vl = __shfl_sync(0xffffffffu, v, l);
            float c0 = base[l * 64 + lane];
            float c1 = base[l * 64 + 32 + lane];
            nv = fmaf(vl, fmaf(M0[q], c0, M1[q] * c1), nv);
        }
        v = nv;
    }
    float wl = M0[NQ - 1] * cl[(s * BOND + lane) * 2] +
               M1[NQ - 1] * cl[(s * BOND + lane) * 2 + 1];
    float ov = v * wl;
#pragma unroll
    for (int o = 16; o; o >>= 1) ov += __shfl_xor_sync(0xffffffffu, ov, o);
    if (lane == 0) g_overlaps[b * S + s] = ov;
}

// ====== Kernel 3: attention softmax + gg (redundant per block) + bias ======
// grid (4), 256 threads; block handles 256 d's.
__global__ void k_attbias(const float* __restrict__ Wd, const float* __restrict__ bd) {
    const int tid = threadIdx.x;
    const int w = tid >> 5;
    const int lane = tid & 31;
    __shared__ float s_gg[B * NQ];

    // attention for batch w (each warp one batch)
    {
        float a0 = g_overlaps[w * S + lane];
        float a1 = g_overlaps[w * S + 32 + lane];
        float m = fmaxf(a0, a1);
#pragma unroll
        for (int o = 16; o; o >>= 1) m = fmaxf(m, __shfl_xor_sync(0xffffffffu, m, o));
        float e0 = __expf(a0 - m);
        float e1 = __expf(a1 - m);
        float ssum = e0 + e1;
#pragma unroll
        for (int o = 16; o; o >>= 1) ssum += __shfl_xor_sync(0xffffffffu, ssum, o);
        const float inv = 1.0f / ssum;
        const float at0 = e0 * inv;
        const float at1 = e1 * inv;
#pragma unroll
        for (int q = 0; q < NQ; ++q) {
            float p = at0 * g_feats[lane * NQ + q] + at1 * g_feats[(32 + lane) * NQ + q];
#pragma unroll
            for (int o = 16; o; o >>= 1) p += __shfl_xor_sync(0xffffffffu, p, o);
            if (lane == 0) s_gg[w * NQ + q] = p;
        }
    }
    __syncthreads();

    // bias[b,d] = bd[d] + sum_c s_gg[b, c&7] * Wd[c,d]
    const int d = blockIdx.x * 256 + tid;
    float acc[B];
    const float bdd = bd[d];
#pragma unroll
    for (int b = 0; b < B; ++b) acc[b] = bdd;
#pragma unroll 4
    for (int c = 0; c < SLOT_DIM; ++c) {
        const float wv = Wd[(size_t)c * D + d];
        const int q = c & 7;
#pragma unroll
        for (int b = 0; b < B; ++b)
            acc[b] = fmaf(s_gg[b * NQ + q], wv, acc[b]);
    }
#pragma unroll
    for (int b = 0; b < B; ++b) g_bias[b * D + d] = acc[b];
}

// ================= Kernel 4: out = x + bias[b, :] broadcast =================
__global__ void k_add(const float* __restrict__ x, float* __restrict__ out) {
    const int blk = blockIdx.x;
    const int b = blk >> 10;               // 1024 blocks per batch
    const size_t row0 = (size_t)blk * 4;
    const int tid = threadIdx.x;
    const float4 bias = reinterpret_cast<const float4*>(g_bias)[b * (D / 4) + tid];
    const float4* xp = reinterpret_cast<const float4*>(x) + row0 * (D / 4);
    float4* op = reinterpret_cast<float4*>(out) + row0 * (D / 4);
#pragma unroll
    for (int r = 0; r < 4; ++r) {
        float4 v = xp[r * (D / 4) + tid];
        v.x += bias.x; v.y += bias.y; v.z += bias.z; v.w += bias.w;
        op[r * (D / 4) + tid] = v;
    }
}

extern "C" void kernel_launch(void* const* d_in, const int* in_sizes, int n_in,
                              void* d_out, int out_size) {
    const float* x  = (const float*)d_in[0];
    const float* Wq = (const float*)d_in[1];
    const float* bq = (const float*)d_in[2];
    const float* Wd = (const float*)d_in[3];
    const float* bd = (const float*)d_in[4];
    const float* cf = (const float*)d_in[5];
    const float* cm = (const float*)d_in[6];
    const float* cl = (const float*)d_in[7];
    float* out = (float*)d_out;

    k_partsum_query<<<dim3(NCHUNK, B), 256>>>(x, Wq, bq);
    k_slots<<<S, 256>>>(cf, cm, cl);
    k_attbias<<<4, 256>>>(Wd, bd);
    k_add<<<(B * T) / 4, 256>>>(x, out);
}

// round 5
// speedup vs baseline: 1.8799x; 1.8799x over previous
#include <cuda_runtime.h>
#include <cstdint>

#define B 8
#define T 4096
#define D 1024
#define S 64
#define SLOT_DIM 256
#define BOND 32
#define NQ 8
#define QDIM 256
#define NB 128          // blocks (<= SM count -> all co-resident)
#define NT 1024         // threads per block
#define PB 16           // blocks per batch in partsum/add phases
#define TB 256          // t-rows per block

// ------- device scratch (no allocations allowed) -------
__device__ float g_part[NB * D];         // [B*PB][D] partial column sums
__device__ float g_m0[B * 32];           // padded: one line per batch
__device__ float g_m1[B * 32];
__device__ float g_overlaps[B * S];
__device__ float g_feats[S * NQ];
__device__ float g_biasp[8 * B * D];     // 8 c-partials of the bias GEMM
__device__ int   g_bar_count;            // zero-init
__device__ int   g_bar_gen;              // monotonically increasing

// ---------------- software grid barrier (all NB blocks resident) ----------------
__device__ __forceinline__ void gbar() {
    __threadfence();              // make this thread's writes device-visible
    __syncthreads();              // all threads in block fenced before signal
    if (threadIdx.x == 0) {
        int gen = *(volatile int*)&g_bar_gen;
        if (atomicAdd(&g_bar_count, 1) == NB - 1) {
            *(volatile int*)&g_bar_count = 0;
            __threadfence();
            *(volatile int*)&g_bar_gen = gen + 1;
        } else {
            while (*(volatile int*)&g_bar_gen == gen) __nanosleep(64);
        }
    }
    __syncthreads();
}

__global__ void __launch_bounds__(NT, 1)
k_fused(const float* __restrict__ x,
        const float* __restrict__ Wq,
        const float* __restrict__ bq,
        const float* __restrict__ Wd,
        const float* __restrict__ bd,
        const float* __restrict__ cf,
        const float* __restrict__ cm,
        const float* __restrict__ cl,
        float* __restrict__ out) {
    __shared__ float smem[12288];   // 48 KB, aliased per phase
    const int blk = blockIdx.x;
    const int tid = threadIdx.x;

    // ================= Phase 1: partial column sums =================
    {
        const int b = blk >> 4;
        const int chunk = blk & 15;
        const int col4 = tid & 255;
        const int rq = tid >> 8;
        const size_t row0 = (size_t)b * T + chunk * TB + rq * 64;
        const float4* xp = reinterpret_cast<const float4*>(x) + row0 * (D / 4) + col4;
        float4 acc = make_float4(0.f, 0.f, 0.f, 0.f);
#pragma unroll 8
        for (int r = 0; r < 64; ++r) {
            float4 v = xp[(size_t)r * 256];
            acc.x += v.x; acc.y += v.y; acc.z += v.z; acc.w += v.w;
        }
        reinterpret_cast<float4*>(smem)[rq * 256 + col4] = acc;
        __syncthreads();
        if (tid < 256) {
            float4 a = reinterpret_cast<float4*>(smem)[tid];
            float4 b4 = reinterpret_cast<float4*>(smem)[256 + tid];
            float4 c4 = reinterpret_cast<float4*>(smem)[512 + tid];
            float4 d4 = reinterpret_cast<float4*>(smem)[768 + tid];
            a.x = (a.x + b4.x) + (c4.x + d4.x);
            a.y = (a.y + b4.y) + (c4.y + d4.y);
            a.z = (a.z + b4.z) + (c4.z + d4.z);
            a.w = (a.w + b4.w) + (c4.w + d4.w);
            reinterpret_cast<float4*>(g_part)[blk * 256 + tid] = a;
        }
    }
    gbar();

    // ================= Phase 2: query (blocks 0..7 = batch) =================
    // NOTE: all __syncthreads here are in UNIFORM control flow (all 1024 threads).
    if (blk < B) {
        float* xs = smem;           // 1024
        float* pr = smem + 1024;    // 1024 (4 x 256)
        float* qa = smem + 2048;    // 256
        float* red = smem + 2304;   // 8
        const int b = blk;
        {
            float acc = 0.f;
#pragma unroll
            for (int p = 0; p < PB; ++p)
                acc += g_part[(b * PB + p) * D + tid];
            xs[tid] = acc * (1.0f / (float)T);
        }
        __syncthreads();

        const int j = tid & 255;
        const int kc = tid >> 8;
        const int k0 = kc * 256;
        {
            float a = 0.f;
#pragma unroll 8
            for (int k = 0; k < 256; ++k)
                a = fmaf(xs[k0 + k], Wq[(size_t)(k0 + k) * QDIM + j], a);
            pr[kc * 256 + j] = a;
        }
        __syncthreads();

        float logit = 0.f;
        if (tid < QDIM)
            logit = (pr[j] + pr[256 + j]) + (pr[512 + j] + pr[768 + j]) + bq[j];

        // softmax over 256 — barriers uniform, data ops guarded
        float m = logit;
#pragma unroll
        for (int o = 16; o; o >>= 1) m = fmaxf(m, __shfl_xor_sync(0xffffffffu, m, o));
        if (tid < QDIM && (tid & 31) == 0) red[tid >> 5] = m;
        __syncthreads();
        float bm = red[0];
#pragma unroll
        for (int i = 1; i < 8; ++i) bm = fmaxf(bm, red[i]);
        float e = (tid < QDIM) ? __expf(logit - bm) : 0.f;
        float ssum = e;
#pragma unroll
        for (int o = 16; o; o >>= 1) ssum += __shfl_xor_sync(0xffffffffu, ssum, o);
        __syncthreads();   // red reads (bm) done before overwrite
        if (tid < QDIM && (tid & 31) == 0) red[tid >> 5] = ssum;
        __syncthreads();
        float tot = 0.f;
#pragma unroll
        for (int i = 0; i < 8; ++i) tot += red[i];
        if (tid < QDIM) qa[j] = e / tot;
        __syncthreads();

        // amplitude means (JAX OOB-clamp to index 255)
        if (tid < 16) {
            const int q = tid & 7;
            const bool one = tid >= 8;
            const int s = 1 << (7 - q);
            const int cin = min(s, 128 / s);
            float a = 0.f;
            const int off = one ? s : 0;
            for (int i = 0; i < cin; ++i) a += qa[i * 2 * s + off];
            a += (float)(s - cin) * qa[QDIM - 1];
            float* dst = one ? g_m1 : g_m0;
            dst[b * 32 + q] = a / (float)s;   // padded stride 32
        }
    }
    gbar();

    // ================= Phase 3: slots (blocks 0..63 = slot) =================
    if (blk < S) {
        const int s = blk;
        {
            const float4* src = reinterpret_cast<const float4*>(cm + (size_t)s * 12288);
            float4* dst = reinterpret_cast<float4*>(smem);
#pragma unroll
            for (int i = 0; i < 3; ++i)
                dst[i * 1024 + tid] = src[i * 1024 + tid];
        }
        __syncthreads();

        if (tid < 256) {
            const int w = tid >> 5;
            const int lane = tid & 31;
            // feats
            float fsum, inv_cnt;
            if (w == 0) {
                fsum = cf[s * 64 + lane] + cf[s * 64 + 32 + lane];
                inv_cnt = 1.0f / 64.0f;
            } else if (w == 7) {
                fsum = cl[s * 64 + lane] + cl[s * 64 + 32 + lane];
                inv_cnt = 1.0f / 64.0f;
            } else {
                const float* base = smem + (w - 1) * 2048;
                fsum = 0.f;
#pragma unroll
                for (int i = 0; i < 64; ++i) fsum += base[i * 32 + lane];
                inv_cnt = 1.0f / 2048.0f;
            }
#pragma unroll
            for (int o = 16; o; o >>= 1) fsum += __shfl_xor_sync(0xffffffffu, fsum, o);
            if (lane == 0) g_feats[s * NQ + w] = fsum * inv_cnt;

            // overlap for batch b = w (m0/m1 via L2)
            const int b = w;
            float M0[NQ], M1[NQ];
#pragma unroll
            for (int q = 0; q < NQ; ++q) {
                M0[q] = __ldcg(&g_m0[b * 32 + q]);
                M1[q] = __ldcg(&g_m1[b * 32 + q]);
            }
            float v = M0[0] * cf[s * 64 + lane] + M1[0] * cf[s * 64 + 32 + lane];
#pragma unroll
            for (int q = 1; q <= NQ - 2; ++q) {
                const float* base = smem + (q - 1) * 2048;
                float nv = 0.f;
#pragma unroll 8
                for (int l = 0; l < BOND; ++l) {
                    float vl = __shfl_sync(0xffffffffu, v, l);
                    float c0 = base[l * 64 + lane];
                    float c1 = base[l * 64 + 32 + lane];
                    nv = fmaf(vl, fmaf(M0[q], c0, M1[q] * c1), nv);
                }
                v = nv;
            }
            float wl = M0[NQ - 1] * cl[(s * BOND + lane) * 2] +
                       M1[NQ - 1] * cl[(s * BOND + lane) * 2 + 1];
            float ov = v * wl;
#pragma unroll
            for (int o = 16; o; o >>= 1) ov += __shfl_xor_sync(0xffffffffu, ov, o);
            if (lane == 0) g_overlaps[b * S + s] = ov;
        }
    }
    gbar();

    // ===== Phase 4: attention + gg (redundant per block) + bias partials =====
    if (blk < 8) {
        float* s_gg = smem;   // 64 floats
        if (tid < 256) {
            const int w = tid >> 5;
            const int lane = tid & 31;
            float a0 = __ldcg(&g_overlaps[w * S + lane]);
            float a1 = __ldcg(&g_overlaps[w * S + 32 + lane]);
            float m = fmaxf(a0, a1);
#pragma unroll
            for (int o = 16; o; o >>= 1) m = fmaxf(m, __shfl_xor_sync(0xffffffffu, m, o));
            float e0 = __expf(a0 - m);
            float e1 = __expf(a1 - m);
            float ssum = e0 + e1;
#pragma unroll
            for (int o = 16; o; o >>= 1) ssum += __shfl_xor_sync(0xffffffffu, ssum, o);
            const float inv = 1.0f / ssum;
            const float at0 = e0 * inv;
            const float at1 = e1 * inv;
#pragma unroll
            for (int q = 0; q < NQ; ++q) {
                float p = at0 * __ldcg(&g_feats[lane * NQ + q]) +
                          at1 * __ldcg(&g_feats[(32 + lane) * NQ + q]);
#pragma unroll
                for (int o = 16; o; o >>= 1) p += __shfl_xor_sync(0xffffffffu, p, o);
                if (lane == 0) s_gg[w * NQ + q] = p;
            }
        }
        __syncthreads();   // uniform within block

        // bias partial: this block handles c in [blk*32, blk*32+32)
        const int p = blk;
        const int d = tid;
        float acc[B];
#pragma unroll
        for (int b2 = 0; b2 < B; ++b2) acc[b2] = 0.f;
#pragma unroll 4
        for (int ci = 0; ci < 32; ++ci) {
            const int c = p * 32 + ci;
            const float wv = Wd[(size_t)c * D + d];
            const int q = ci & 7;   // (p*32+ci) & 7 == ci & 7
#pragma unroll
            for (int b2 = 0; b2 < B; ++b2)
                acc[b2] = fmaf(s_gg[b2 * NQ + q], wv, acc[b2]);
        }
#pragma unroll
        for (int b2 = 0; b2 < B; ++b2)
            g_biasp[((size_t)p * B + b2) * D + d] = acc[b2];
    }
    gbar();

    // ================= Phase 5: out = x + bias (reversed block order) =================
    {
        const int kk = (NB - 1) - blk;   // reversed for L2 retention of x
        const int b = kk >> 4;
        const int chunk = kk & 15;

        // fold bias partials + bd into shared
        {
            float v = bd[tid];
#pragma unroll
            for (int p = 0; p < 8; ++p)
                v += __ldcg(&g_biasp[((size_t)p * B + b) * D + tid]);
            smem[tid] = v;
        }
        __syncthreads();

        const int col4 = tid & 255;
        const int rq = tid >> 8;
        const size_t row0 = (size_t)b * T + chunk * TB + rq * 64;
        const float4* xp = reinterpret_cast<const float4*>(x) + row0 * (D / 4) + col4;
        float4* op = reinterpret_cast<float4*>(out) + row0 * (D / 4) + col4;
        const float4 bias4 = reinterpret_cast<float4*>(smem)[col4];
#pragma unroll 8
        for (int r = 0; r < 64; ++r) {
            float4 v = xp[(size_t)r * 256];
            v.x += bias4.x; v.y += bias4.y; v.z += bias4.z; v.w += bias4.w;
            __stcs(&op[(size_t)r * 256], v);   // streaming store: keep x in L2
        }
    }
}

extern "C" void kernel_launch(void* const* d_in, const int* in_sizes, int n_in,
                              void* d_out, int out_size) {
    const float* x  = (const float*)d_in[0];
    const float* Wq = (const float*)d_in[1];
    const float* bq = (const float*)d_in[2];
    const float* Wd = (const float*)d_in[3];
    const float* bd = (const float*)d_in[4];
    const float* cf = (const float*)d_in[5];
    const float* cm = (const float*)d_in[6];
    const float* cl = (const float*)d_in[7];
    float* out = (float*)d_out;

    k_fused<<<NB, NT>>>(x, Wq, bq, Wd, bd, cf, cm, cl, out);
}